// round 1
// baseline (speedup 1.0000x reference)
#include <cuda_runtime.h>

// Problem constants (fixed by the reference)
#define B_SZ 4096
#define T_SZ 2048
#define DDIM 3
#define SDIM 5
#define HIDD 32
#define UPL  8   // hidden units per lane
// 4 lanes per row, 8 rows per warp, 32 rows per 128-thread block, 128 blocks

__device__ __forceinline__ float fast_tanh(float x) {
    // tanh(x) = 1 - 2/(exp(2x)+1); MUFU.EX2 + MUFU.RCP, rel err ~1e-6.
    float e = __expf(x + x);
    float r = __fdividef(2.0f, e + 1.0f);
    return 1.0f - r;
}

__global__ void __launch_bounds__(128, 1)
msc_seq_kernel(const float* __restrict__ delta_seq,  // [B, T, 3]
               const float* __restrict__ state_0,    // [B, 5]
               const float* __restrict__ W1,         // [8, 32]
               const float* __restrict__ b1,         // [32]
               const float* __restrict__ W2,         // [32, 32]
               const float* __restrict__ b2,         // [32]
               const float* __restrict__ W3,         // [32, 5]
               const float* __restrict__ b3,         // [5]
               float* __restrict__ out)              // [B, T, 5]
{
    __shared__ __align__(16) float sW2[HIDD * HIDD];

    // Cooperative W2 load: 1024 floats = 256 float4 by 128 threads
    {
        const float4* src = (const float4*)W2;
        float4* dst = (float4*)sW2;
        dst[threadIdx.x]       = src[threadIdx.x];
        dst[threadIdx.x + 128] = src[threadIdx.x + 128];
    }
    __syncthreads();

    const int q     = threadIdx.x & 3;                    // lane-within-row
    const int row   = blockIdx.x * 32 + (threadIdx.x >> 2);
    const int ubase = q * UPL;                            // first of my 8 hidden units

    // Weight slices held in registers for all 2048 steps
    float w1[8][UPL], b1v[UPL], b2v[UPL], w3[UPL][SDIM], b3v[SDIM];
    #pragma unroll
    for (int u = 0; u < UPL; ++u) {
        b1v[u] = b1[ubase + u];
        b2v[u] = b2[ubase + u];
        #pragma unroll
        for (int i = 0; i < 8; ++i) w1[i][u] = W1[i * HIDD + ubase + u];
        #pragma unroll
        for (int s = 0; s < SDIM; ++s) w3[u][s] = W3[(ubase + u) * SDIM + s];
    }
    #pragma unroll
    for (int s = 0; s < SDIM; ++s) b3v[s] = b3[s];

    float st[SDIM];
    #pragma unroll
    for (int s = 0; s < SDIM; ++s) st[s] = state_0[row * SDIM + s];

    const float* dptr = delta_seq + (size_t)row * T_SZ * DDIM;
    float* optr = out + (size_t)row * T_SZ * SDIM;

    // Prefetch delta[t=0]
    float dn0 = __ldg(dptr + 0), dn1 = __ldg(dptr + 1), dn2 = __ldg(dptr + 2);

    for (int t = 0; t < T_SZ; ++t) {
        const float d0 = dn0, d1 = dn1, d2 = dn2;
        // Software-pipelined prefetch of next step's delta (clamped at the end)
        const int tn = (t + 1 < T_SZ) ? (t + 1) : t;
        const float* dp = dptr + tn * DDIM;
        dn0 = __ldg(dp + 0); dn1 = __ldg(dp + 1); dn2 = __ldg(dp + 2);

        // ---- layer 1: h1 = tanh([state|delta] @ W1 + b1), my 8 units ----
        float h1[UPL];
        #pragma unroll
        for (int u = 0; u < UPL; ++u) {
            float a = b1v[u];
            a = fmaf(st[0], w1[0][u], a);
            a = fmaf(st[1], w1[1][u], a);
            a = fmaf(st[2], w1[2][u], a);
            a = fmaf(st[3], w1[3][u], a);
            a = fmaf(st[4], w1[4][u], a);
            a = fmaf(d0,    w1[5][u], a);
            a = fmaf(d1,    w1[6][u], a);
            a = fmaf(d2,    w1[7][u], a);
            h1[u] = fast_tanh(a);
        }

        // ---- layer 2: h2 = tanh(h1 @ W2 + b2) ----
        // h1 lives 8-per-lane across my 4-lane group; broadcast via shfl (width 4).
        float h2[UPL];
        #pragma unroll
        for (int u = 0; u < UPL; ++u) h2[u] = b2v[u];
        #pragma unroll
        for (int i = 0; i < HIDD; ++i) {
            float hv = __shfl_sync(0xffffffffu, h1[i & 7], i >> 3, 4);
            float4 wa = *(const float4*)&sW2[i * HIDD + ubase];
            float4 wb = *(const float4*)&sW2[i * HIDD + ubase + 4];
            h2[0] = fmaf(hv, wa.x, h2[0]);
            h2[1] = fmaf(hv, wa.y, h2[1]);
            h2[2] = fmaf(hv, wa.z, h2[2]);
            h2[3] = fmaf(hv, wa.w, h2[3]);
            h2[4] = fmaf(hv, wb.x, h2[4]);
            h2[5] = fmaf(hv, wb.y, h2[5]);
            h2[6] = fmaf(hv, wb.z, h2[6]);
            h2[7] = fmaf(hv, wb.w, h2[7]);
        }
        #pragma unroll
        for (int u = 0; u < UPL; ++u) h2[u] = fast_tanh(h2[u]);

        // ---- layer 3 + residual: state += h2 @ W3 + b3 ----
        float p[SDIM];
        #pragma unroll
        for (int s = 0; s < SDIM; ++s) {
            float a = 0.0f;
            #pragma unroll
            for (int u = 0; u < UPL; ++u) a = fmaf(h2[u], w3[u][s], a);
            p[s] = a;
        }
        #pragma unroll
        for (int s = 0; s < SDIM; ++s) {
            p[s] += __shfl_xor_sync(0xffffffffu, p[s], 1);  // stays inside 4-group
            p[s] += __shfl_xor_sync(0xffffffffu, p[s], 2);
            st[s] = st[s] + p[s] + b3v[s];
        }

        // ---- store ys[row, t, :]: lane q writes elem q; q==0 also writes elem 4 ----
        float* o = optr + t * SDIM;
        float v = (q == 0) ? st[0] : (q == 1) ? st[1] : (q == 2) ? st[2] : st[3];
        o[q] = v;
        if (q == 0) o[4] = st[4];
    }
}

extern "C" void kernel_launch(void* const* d_in, const int* in_sizes, int n_in,
                              void* d_out, int out_size) {
    (void)in_sizes; (void)n_in; (void)out_size;
    const float* delta_seq = (const float*)d_in[0];
    const float* state_0   = (const float*)d_in[1];
    const float* W1        = (const float*)d_in[2];
    const float* b1        = (const float*)d_in[3];
    const float* W2        = (const float*)d_in[4];
    const float* b2        = (const float*)d_in[5];
    const float* W3        = (const float*)d_in[6];
    const float* b3        = (const float*)d_in[7];
    float* out             = (float*)d_out;

    msc_seq_kernel<<<B_SZ / 32, 128>>>(delta_seq, state_0, W1, b1, W2, b2, W3, b3, out);
}

// round 2
// speedup vs baseline: 1.4717x; 1.4717x over previous
#include <cuda_runtime.h>

// Problem constants (fixed by the reference)
#define B_SZ 4096
#define T_SZ 2048

typedef unsigned long long u64;

// ---- f32x2 packed-math helpers (sm_103a) ----
__device__ __forceinline__ u64 pack2(float lo, float hi) {
    u64 r; asm("mov.b64 %0,{%1,%2};" : "=l"(r) : "f"(lo), "f"(hi)); return r;
}
__device__ __forceinline__ u64 bcast2(float v) { return pack2(v, v); }
__device__ __forceinline__ void unpack2(u64 p, float& a, float& b) {
    asm("mov.b64 {%0,%1},%2;" : "=f"(a), "=f"(b) : "l"(p));
}
__device__ __forceinline__ u64 fma2(u64 a, u64 b, u64 c) {
    u64 d; asm("fma.rn.f32x2 %0,%1,%2,%3;" : "=l"(d) : "l"(a), "l"(b), "l"(c)); return d;
}
__device__ __forceinline__ u64 mul2(u64 a, u64 b) {
    u64 d; asm("mul.rn.f32x2 %0,%1,%2;" : "=l"(d) : "l"(a), "l"(b)); return d;
}

__device__ __forceinline__ float fast_tanh(float x) {
    // tanh(x) = 1 - 2/(exp(2x)+1); rel err ~1e-6 (validated: rel_err 1.04e-5 end-to-end)
    float e = __expf(x + x);
    float r = __fdividef(2.0f, e + 1.0f);
    return 1.0f - r;
}

// Layout: 8 lanes per row. Lane l (=tid&7) owns hidden units / W2 columns
// {2l, 2l+1, 16+2l, 16+2l+1} (two contiguous f32x2 pairs). All of W1/W2/W3
// slices live in registers; h1 is exchanged with static shfl broadcasts.
__global__ void __launch_bounds__(256, 1)
msc_seq_kernel(const float* __restrict__ delta_seq,  // [B, T, 3]
               const float* __restrict__ state_0,    // [B, 5]
               const float* __restrict__ W1,         // [8, 32]
               const float* __restrict__ b1,         // [32]
               const float* __restrict__ W2,         // [32, 32]
               const float* __restrict__ b2,         // [32]
               const float* __restrict__ W3,         // [32, 5]
               const float* __restrict__ b3,         // [5]
               float* __restrict__ out)              // [B, T, 5]
{
    const int tid = threadIdx.x;
    const int l   = tid & 7;                       // lane within row
    const int row = blockIdx.x * 32 + (tid >> 3);  // 32 rows per 256-thread CTA
    const int c0  = 2 * l;                         // first owned column (pair A)
    const int c1  = 16 + 2 * l;                    // first owned column (pair B)

    // ---- register-resident weight slices (loaded once, reused 2048x) ----
    u64 w1p[8][2];   // W1[i][c0..c0+1], W1[i][c1..c1+1]
    #pragma unroll
    for (int i = 0; i < 8; ++i) {
        float2 a = *(const float2*)&W1[i * 32 + c0];
        float2 b = *(const float2*)&W1[i * 32 + c1];
        w1p[i][0] = pack2(a.x, a.y);
        w1p[i][1] = pack2(b.x, b.y);
    }
    u64 w2p[32][2];  // W2[i][c0..c0+1], W2[i][c1..c1+1]
    #pragma unroll
    for (int i = 0; i < 32; ++i) {
        float2 a = *(const float2*)&W2[i * 32 + c0];
        float2 b = *(const float2*)&W2[i * 32 + c1];
        w2p[i][0] = pack2(a.x, a.y);
        w2p[i][1] = pack2(b.x, b.y);
    }
    u64 b1pA, b1pB, b2pA, b2pB;
    { float2 a = *(const float2*)&b1[c0]; b1pA = pack2(a.x, a.y);
      float2 b = *(const float2*)&b1[c1]; b1pB = pack2(b.x, b.y);
      float2 c = *(const float2*)&b2[c0]; b2pA = pack2(c.x, c.y);
      float2 d = *(const float2*)&b2[c1]; b2pB = pack2(d.x, d.y); }

    // W3 rows for owned units (rows c0, c0+1, c1, c1+1), packed by output pairs
    u64 w3p01[4], w3p23[4];
    float w3s4[4];
    {
        const int ru[4] = { c0, c0 + 1, c1, c1 + 1 };
        #pragma unroll
        for (int u = 0; u < 4; ++u) {
            const float* wr = W3 + ru[u] * 5;
            w3p01[u] = pack2(wr[0], wr[1]);
            w3p23[u] = pack2(wr[2], wr[3]);
            w3s4[u]  = wr[4];
        }
    }
    const float b30 = b3[0], b31 = b3[1], b32 = b3[2], b33 = b3[3], b34 = b3[4];

    float s0 = state_0[row * 5 + 0], s1 = state_0[row * 5 + 1],
          s2 = state_0[row * 5 + 2], s3 = state_0[row * 5 + 3],
          s4 = state_0[row * 5 + 4];

    const float* dptr = delta_seq + (size_t)row * T_SZ * 3;
    float* optr = out + (size_t)row * T_SZ * 5;

    // Prefetch delta[t=0]
    float dn0 = __ldg(dptr + 0), dn1 = __ldg(dptr + 1), dn2 = __ldg(dptr + 2);

    for (int t = 0; t < T_SZ; ++t) {
        const float d0 = dn0, d1 = dn1, d2 = dn2;
        const int tn = (t + 1 < T_SZ) ? (t + 1) : t;
        const float* dp = dptr + tn * 3;
        dn0 = __ldg(dp + 0); dn1 = __ldg(dp + 1); dn2 = __ldg(dp + 2);

        // ---- layer 1: h1 = tanh(x @ W1 + b1), own 4 units (2 f32x2 pairs) ----
        u64 xs[8];
        xs[0] = bcast2(s0); xs[1] = bcast2(s1); xs[2] = bcast2(s2);
        xs[3] = bcast2(s3); xs[4] = bcast2(s4);
        xs[5] = bcast2(d0); xs[6] = bcast2(d1); xs[7] = bcast2(d2);

        u64 pA = b1pA, pB = b1pB;
        #pragma unroll
        for (int i = 0; i < 8; ++i) {
            pA = fma2(xs[i], w1p[i][0], pA);
            pB = fma2(xs[i], w1p[i][1], pB);
        }
        float hh[4];
        unpack2(pA, hh[0], hh[1]);
        unpack2(pB, hh[2], hh[3]);
        hh[0] = fast_tanh(hh[0]); hh[1] = fast_tanh(hh[1]);
        hh[2] = fast_tanh(hh[2]); hh[3] = fast_tanh(hh[3]);

        // ---- layer 2: h2 = tanh(h1 @ W2 + b2), W2 columns in registers ----
        // h1[i] is owned by lane (i&15)>>1, local slot (i&1) + 2*(i>>4).
        u64 cA = b2pA, cB = b2pB;
        #pragma unroll
        for (int i = 0; i < 32; ++i) {
            const int src = (i & 15) >> 1;          // compile-time constants
            const int slot = (i & 1) + ((i >> 4) << 1);
            float hv = __shfl_sync(0xffffffffu, hh[slot], src, 8);
            u64 hb = bcast2(hv);
            cA = fma2(hb, w2p[i][0], cA);
            cB = fma2(hb, w2p[i][1], cB);
        }
        float g[4];
        unpack2(cA, g[0], g[1]);
        unpack2(cB, g[2], g[3]);
        g[0] = fast_tanh(g[0]); g[1] = fast_tanh(g[1]);
        g[2] = fast_tanh(g[2]); g[3] = fast_tanh(g[3]);

        // ---- layer 3 + residual: state += h2 @ W3 + b3 ----
        u64 hb0 = bcast2(g[0]);
        u64 p01 = mul2(hb0, w3p01[0]);
        u64 p23 = mul2(hb0, w3p23[0]);
        float p4 = g[0] * w3s4[0];
        #pragma unroll
        for (int u = 1; u < 4; ++u) {
            u64 hb = bcast2(g[u]);
            p01 = fma2(hb, w3p01[u], p01);
            p23 = fma2(hb, w3p23[u], p23);
            p4  = fmaf(g[u], w3s4[u], p4);
        }
        float p0, p1, p2, p3;
        unpack2(p01, p0, p1);
        unpack2(p23, p2, p3);

        // allreduce across the 8 lanes of this row (xor 1,2,4 stays in-group)
        #pragma unroll
        for (int d = 1; d < 8; d <<= 1) {
            p0 += __shfl_xor_sync(0xffffffffu, p0, d);
            p1 += __shfl_xor_sync(0xffffffffu, p1, d);
            p2 += __shfl_xor_sync(0xffffffffu, p2, d);
            p3 += __shfl_xor_sync(0xffffffffu, p3, d);
            p4 += __shfl_xor_sync(0xffffffffu, p4, d);
        }
        s0 += p0 + b30; s1 += p1 + b31; s2 += p2 + b32;
        s3 += p3 + b33; s4 += p4 + b34;

        // ---- store ys[row, t, :]: lanes 0..4 each write one element ----
        float* o = optr + t * 5;
        if (l < 5) {
            float v = (l == 0) ? s0 : (l == 1) ? s1 : (l == 2) ? s2
                    : (l == 3) ? s3 : s4;
            o[l] = v;
        }
    }
}

extern "C" void kernel_launch(void* const* d_in, const int* in_sizes, int n_in,
                              void* d_out, int out_size) {
    (void)in_sizes; (void)n_in; (void)out_size;
    const float* delta_seq = (const float*)d_in[0];
    const float* state_0   = (const float*)d_in[1];
    const float* W1        = (const float*)d_in[2];
    const float* b1        = (const float*)d_in[3];
    const float* W2        = (const float*)d_in[4];
    const float* b2        = (const float*)d_in[5];
    const float* W3        = (const float*)d_in[6];
    const float* b3        = (const float*)d_in[7];
    float* out             = (float*)d_out;

    msc_seq_kernel<<<B_SZ / 32, 256>>>(delta_seq, state_0, W1, b1, W2, b2, W3, b3, out);
}

// round 3
// speedup vs baseline: 1.7420x; 1.1837x over previous
#include <cuda_runtime.h>

// Problem constants (fixed by the reference)
#define B_SZ 4096
#define T_SZ 2048

typedef unsigned long long u64;

// ---- f32x2 packed-math helpers (sm_103a) ----
__device__ __forceinline__ u64 pack2(float lo, float hi) {
    u64 r; asm("mov.b64 %0,{%1,%2};" : "=l"(r) : "f"(lo), "f"(hi)); return r;
}
__device__ __forceinline__ u64 bcast2(float v) { return pack2(v, v); }
__device__ __forceinline__ void unpack2(u64 p, float& a, float& b) {
    asm("mov.b64 {%0,%1},%2;" : "=f"(a), "=f"(b) : "l"(p));
}
__device__ __forceinline__ u64 fma2(u64 a, u64 b, u64 c) {
    u64 d; asm("fma.rn.f32x2 %0,%1,%2,%3;" : "=l"(d) : "l"(a), "l"(b), "l"(c)); return d;
}

__device__ __forceinline__ float fast_tanh(float x) {
    // tanh(x) = 1 - 2/(exp2(x*2*log2e)+1); ~1e-6 rel err (validated 1.3e-5 end-to-end)
    float e = exp2f(x * 2.885390082f);
    float r = __fdividef(2.0f, e + 1.0f);
    return 1.0f - r;
}

// Layout: 8 lanes per row, 4 rows per warp, 32 rows per 256-thread CTA.
// Lane l owns hidden columns {2l,2l+1} and {16+2l,16+2l+1} for layers 1&2.
// Activations exchanged through padded smem as packed f32x2 pairs (i-packed),
// so layer-2/3 FMAs consume them with NO broadcast MOVs and NO shfl.
// Layer 3: lanes 0..4 each own one state element (full 32-term dot), state
// redistributed with 5 broadcast shfls.
__global__ void __launch_bounds__(256, 1)
msc_seq_kernel(const float* __restrict__ delta_seq,  // [B, T, 3]
               const float* __restrict__ state_0,    // [B, 5]
               const float* __restrict__ W1,         // [8, 32]
               const float* __restrict__ b1,         // [32]
               const float* __restrict__ W2,         // [32, 32]
               const float* __restrict__ b2,         // [32]
               const float* __restrict__ W3,         // [32, 5]
               const float* __restrict__ b3,         // [5]
               float* __restrict__ out)              // [B, T, 5]
{
    // Row stride 18 u64 = 144B (odd multiple of 16B) => 4 warp-rows hit
    // distinct banks on the broadcast LDS.128s. 16 pairs used + 2 pad.
    __shared__ __align__(16) u64 h1buf[32][18];
    __shared__ __align__(16) u64 h2buf[32][18];

    const int tid = threadIdx.x;
    const int l   = tid & 7;                 // lane within row
    const int r   = tid >> 3;                // row within CTA (0..31)
    const int row = blockIdx.x * 32 + r;
    const int c0  = 2 * l;                   // owned column pair A
    const int c1  = 16 + 2 * l;              // owned column pair B

    // ---- layer-1 weights, column-packed: (W1[i][c0],W1[i][c0+1]) etc ----
    u64 w1p[8][2];
    #pragma unroll
    for (int i = 0; i < 8; ++i) {
        w1p[i][0] = pack2(W1[i * 32 + c0], W1[i * 32 + c0 + 1]);
        w1p[i][1] = pack2(W1[i * 32 + c1], W1[i * 32 + c1 + 1]);
    }
    const u64 b1pA = pack2(b1[c0], b1[c0 + 1]);
    const u64 b1pB = pack2(b1[c1], b1[c1 + 1]);

    // ---- layer-2 weights, i-packed per owned column ----
    // w2c[c][j] = (W2[2j][col_c], W2[2j+1][col_c])
    u64 w2c[4][16];
    {
        const int cols[4] = { c0, c0 + 1, c1, c1 + 1 };
        #pragma unroll
        for (int c = 0; c < 4; ++c)
            #pragma unroll
            for (int j = 0; j < 16; ++j)
                w2c[c][j] = pack2(W2[(2 * j) * 32 + cols[c]],
                                  (float)W2[(2 * j + 1) * 32 + cols[c]]);
    }
    // bias folded into accumulator init: acc = (b2[c], 0)
    u64 b2i[4];
    {
        const int cols[4] = { c0, c0 + 1, c1, c1 + 1 };
        #pragma unroll
        for (int c = 0; c < 4; ++c) b2i[c] = pack2(b2[cols[c]], 0.0f);
    }

    // ---- layer-3 weights: my output element s, i-packed down W3 column s ----
    const int s = (l < 5) ? l : 0;
    u64 w3c[16];
    #pragma unroll
    for (int j = 0; j < 16; ++j)
        w3c[j] = pack2(W3[(2 * j) * 5 + s], W3[(2 * j + 1) * 5 + s]);
    const u64 b3i = pack2(b3[s], 0.0f);

    float mystate = state_0[row * 5 + s];    // lanes 5..7 hold a dup, never read

    const float* dptr = delta_seq + (size_t)row * T_SZ * 3;
    float* optr = out + (size_t)row * T_SZ * 5;

    // Prefetch delta[t=0]
    float dn0 = __ldg(dptr + 0), dn1 = __ldg(dptr + 1), dn2 = __ldg(dptr + 2);

    for (int t = 0; t < T_SZ; ++t) {
        const float d0 = dn0, d1 = dn1, d2 = dn2;
        const int tn = (t + 1 < T_SZ) ? (t + 1) : t;
        const float* dp = dptr + tn * 3;
        dn0 = __ldg(dp + 0); dn1 = __ldg(dp + 1); dn2 = __ldg(dp + 2);

        // broadcast state elements from owner lanes (5 shfls)
        const float s0 = __shfl_sync(0xffffffffu, mystate, 0, 8);
        const float s1 = __shfl_sync(0xffffffffu, mystate, 1, 8);
        const float s2 = __shfl_sync(0xffffffffu, mystate, 2, 8);
        const float s3 = __shfl_sync(0xffffffffu, mystate, 3, 8);
        const float s4 = __shfl_sync(0xffffffffu, mystate, 4, 8);

        // ---- layer 1: column-packed, own 4 units ----
        u64 aA = b1pA, aB = b1pB;
        {
            u64 x;
            x = bcast2(s0); aA = fma2(x, w1p[0][0], aA); aB = fma2(x, w1p[0][1], aB);
            x = bcast2(s1); aA = fma2(x, w1p[1][0], aA); aB = fma2(x, w1p[1][1], aB);
            x = bcast2(s2); aA = fma2(x, w1p[2][0], aA); aB = fma2(x, w1p[2][1], aB);
            x = bcast2(s3); aA = fma2(x, w1p[3][0], aA); aB = fma2(x, w1p[3][1], aB);
            x = bcast2(s4); aA = fma2(x, w1p[4][0], aA); aB = fma2(x, w1p[4][1], aB);
            x = bcast2(d0); aA = fma2(x, w1p[5][0], aA); aB = fma2(x, w1p[5][1], aB);
            x = bcast2(d1); aA = fma2(x, w1p[6][0], aA); aB = fma2(x, w1p[6][1], aB);
            x = bcast2(d2); aA = fma2(x, w1p[7][0], aA); aB = fma2(x, w1p[7][1], aB);
        }
        float h0, h1v, h2v, h3;
        unpack2(aA, h0, h1v);
        unpack2(aB, h2v, h3);
        h0 = fast_tanh(h0); h1v = fast_tanh(h1v);
        h2v = fast_tanh(h2v); h3 = fast_tanh(h3);

        // publish h1 pairs: slot l = (h[2l],h[2l+1]), slot 8+l = (h[16+2l],...)
        h1buf[r][l]     = pack2(h0, h1v);
        h1buf[r][8 + l] = pack2(h2v, h3);
        __syncwarp();

        // ---- layer 2: i-packed, 16 fma2 per owned column ----
        u64 acc0 = b2i[0], acc1 = b2i[1], acc2 = b2i[2], acc3 = b2i[3];
        #pragma unroll
        for (int k = 0; k < 8; ++k) {
            ulonglong2 hp = *(const ulonglong2*)&h1buf[r][2 * k];
            acc0 = fma2(hp.x, w2c[0][2 * k], acc0);
            acc1 = fma2(hp.x, w2c[1][2 * k], acc1);
            acc2 = fma2(hp.x, w2c[2][2 * k], acc2);
            acc3 = fma2(hp.x, w2c[3][2 * k], acc3);
            acc0 = fma2(hp.y, w2c[0][2 * k + 1], acc0);
            acc1 = fma2(hp.y, w2c[1][2 * k + 1], acc1);
            acc2 = fma2(hp.y, w2c[2][2 * k + 1], acc2);
            acc3 = fma2(hp.y, w2c[3][2 * k + 1], acc3);
        }
        float g0, g1, g2, g3;
        { float lo, hi;
          unpack2(acc0, lo, hi); g0 = fast_tanh(lo + hi);
          unpack2(acc1, lo, hi); g1 = fast_tanh(lo + hi);
          unpack2(acc2, lo, hi); g2 = fast_tanh(lo + hi);
          unpack2(acc3, lo, hi); g3 = fast_tanh(lo + hi); }

        // publish h2 pairs
        h2buf[r][l]     = pack2(g0, g1);
        h2buf[r][8 + l] = pack2(g2, g3);
        __syncwarp();

        // ---- layer 3: lane s computes full 32-term dot for state[s] ----
        u64 pa = b3i, pb = pack2(0.0f, 0.0f);
        #pragma unroll
        for (int k = 0; k < 8; ++k) {
            ulonglong2 hp = *(const ulonglong2*)&h2buf[r][2 * k];
            pa = fma2(hp.x, w3c[2 * k], pa);
            pb = fma2(hp.y, w3c[2 * k + 1], pb);
        }
        float pl0, ph0, pl1, ph1;
        unpack2(pa, pl0, ph0);
        unpack2(pb, pl1, ph1);
        mystate += (pl0 + ph0) + (pl1 + ph1);

        // ---- store ys[row, t, s] ----
        if (l < 5) optr[t * 5 + l] = mystate;
    }
}

extern "C" void kernel_launch(void* const* d_in, const int* in_sizes, int n_in,
                              void* d_out, int out_size) {
    (void)in_sizes; (void)n_in; (void)out_size;
    const float* delta_seq = (const float*)d_in[0];
    const float* state_0   = (const float*)d_in[1];
    const float* W1        = (const float*)d_in[2];
    const float* b1        = (const float*)d_in[3];
    const float* W2        = (const float*)d_in[4];
    const float* b2        = (const float*)d_in[5];
    const float* W3        = (const float*)d_in[6];
    const float* b3        = (const float*)d_in[7];
    float* out             = (float*)d_out;

    msc_seq_kernel<<<B_SZ / 32, 256>>>(delta_seq, state_0, W1, b1, W2, b2, W3, b3, out);
}